// round 6
// baseline (speedup 1.0000x reference)
#include <cuda_runtime.h>
#include <cuda_bf16.h>
#include <cstdint>

// EdgeConvE: out[v,h] = sum_w A[v,w] * relu(S[v,h] + T[w,h] + sum_e E[v,w,e]*We[e,h])
// N=1024, F=32, E_ATTR=8, H=64.
// R6: tf32 mma m16n8k8; warp handles 4 n-tiles (32 h) -> ~60 regs -> 4 CTA/SM;
// block = 4 v x 2 h-halves; K-permuted frags so E loads are 2x LDG.64;
// fused deterministic last-block combine.

#define N_NODES 1024
#define F_NODE  32
#define E_ATTR  8
#define H_OUT   64

__device__ __forceinline__ uint32_t to_tf32(float f) {
    uint32_t u; asm("cvt.rna.tf32.f32 %0, %1;" : "=r"(u) : "f"(f)); return u;
}

// ---------- scratch ----------
__device__ float  g_S [N_NODES * H_OUT];             // 256 KB
__device__ float4 g_Tf[(N_NODES / 16) * 8 * 32];     // 256 KB: T in MMA-C frag layout
__device__ float  g_part[2][N_NODES * H_OUT];        // 512 KB
__device__ int    g_cnt[N_NODES / 4];                // last-block tickets (self-reset)

// ---------- kernel 1: S + fragged T ----------
// grid 256, block 256: 4 v per block, one (vl,h) per thread.
__global__ void __launch_bounds__(256)
prep_st(const float* __restrict__ X, const float* __restrict__ W,
        const float* __restrict__ b) {
    __shared__ float ws[2 * F_NODE * H_OUT];   // 16 KB
    __shared__ float xs[4][F_NODE];
    const int tid = threadIdx.x;
    const int v0  = blockIdx.x * 4;

    const float4* W4 = reinterpret_cast<const float4*>(W);
    float4* ws4 = reinterpret_cast<float4*>(ws);
#pragma unroll
    for (int i = 0; i < 4; i++) ws4[tid + 256 * i] = W4[tid + 256 * i];
    if (tid < 32)
        reinterpret_cast<float4*>(xs)[tid] =
            reinterpret_cast<const float4*>(X + v0 * F_NODE)[tid];
    __syncthreads();

    const int h  = tid & 63;
    const int vl = tid >> 6;
    float s = __ldg(&b[h]), t = 0.0f;
#pragma unroll
    for (int f = 0; f < F_NODE; f++) {
        float x  = xs[vl][f];
        float wv = ws[f * H_OUT + h];
        float wd = ws[(f + F_NODE) * H_OUT + h];
        s = fmaf(x, wv - wd, s);
        t = fmaf(x, wd, t);
    }
    const int v = v0 + vl;
    g_S[v * H_OUT + h] = s;
    // scatter T into MMA-C frag layout:
    const int wt   = v >> 4;
    const int gid  = v & 7;
    const int rs   = (v >> 3) & 1;
    const int t4   = (h >> 1) & 3;
    const int j    = h >> 3;
    const int elem = (h & 1) + 2 * rs;
    reinterpret_cast<float*>(g_Tf)[(((wt * 8 + j) * 32) + gid * 4 + t4) * 4 + elem] = t;
}

// ---------- kernel 2: main ----------
// Block: 8 warps = 4 v x 2 h-halves, scanning one w-half. Grid 512, 4 CTA/SM.
// K-permutation: MMA k-slot t4 <-> attr 2*t4, slot t4+4 <-> attr 2*t4+1
// (applied consistently to E A-frags and We B-frags; result invariant).
__global__ void __launch_bounds__(256, 4)
edge_main(const float* __restrict__ E, const int* __restrict__ A,
          const float* __restrict__ W, float* __restrict__ out) {
    const int vg   = blockIdx.x >> 1;
    const int half = blockIdx.x & 1;
    const int warp = threadIdx.x >> 5;
    const int lane = threadIdx.x & 31;
    const int gid  = lane >> 2;            // 0..7
    const int t4   = lane & 3;             // 0..3
    const int v    = vg * 4 + (warp & 3);
    const int hh   = warp >> 2;            // h-half: j in [hh*4, hh*4+4)

    // B frags (We in tf32), permuted-K rows 2t4 and 2t4+1
    uint32_t bf0[4], bf1[4];
#pragma unroll
    for (int jj = 0; jj < 4; jj++) {
        const int j = hh * 4 + jj;
        bf0[jj] = to_tf32(W[(2 * F_NODE + 2 * t4)     * H_OUT + j * 8 + gid]);
        bf1[jj] = to_tf32(W[(2 * F_NODE + 2 * t4 + 1) * H_OUT + j * 8 + gid]);
    }
    float2 sj[4];
#pragma unroll
    for (int jj = 0; jj < 4; jj++)
        sj[jj] = *(const float2*)&g_S[v * H_OUT + (hh * 4 + jj) * 8 + 2 * t4];

    float acc0[4], acc1[4];
#pragma unroll
    for (int jj = 0; jj < 4; jj++) { acc0[jj] = 0.0f; acc1[jj] = 0.0f; }

    const float* __restrict__ Ev = E + (size_t)v * (N_NODES * E_ATTR);
    const int*   __restrict__ Av = A + v * N_NODES;
    const float4* __restrict__ Tf = g_Tf;

    const int wt0 = half * 32;
#pragma unroll 2
    for (int wt = wt0; wt < wt0 + 32; wt++) {
        const int r0 = wt * 16 + gid;
        const int r1 = r0 + 8;
        // E A-frag, permuted K: one LDG.64 per row
        float2 e0 = *(const float2*)&Ev[r0 * E_ATTR + 2 * t4];
        float2 e1 = *(const float2*)&Ev[r1 * E_ATTR + 2 * t4];
        uint32_t a0 = to_tf32(e0.x);   // k-slot t4      (attr 2t4)
        uint32_t a2 = to_tf32(e0.y);   // k-slot t4+4    (attr 2t4+1)
        uint32_t a1 = to_tf32(e1.x);
        uint32_t a3 = to_tf32(e1.y);
        float aF0 = (float)Av[r0];
        float aF1 = (float)Av[r1];
#pragma unroll
        for (int jj = 0; jj < 4; jj++) {
            const int j = hh * 4 + jj;
            float4 c = Tf[(wt * 8 + j) * 32 + lane];   // coalesced, L1-shared
            float c0 = c.x + sj[jj].x;
            float c1 = c.y + sj[jj].y;
            float c2 = c.z + sj[jj].x;
            float c3 = c.w + sj[jj].y;
            float d0, d1, d2, d3;
            asm("mma.sync.aligned.m16n8k8.row.col.f32.tf32.tf32.f32 "
                "{%0,%1,%2,%3}, {%4,%5,%6,%7}, {%8,%9}, {%10,%11,%12,%13};"
                : "=f"(d0), "=f"(d1), "=f"(d2), "=f"(d3)
                : "r"(a0), "r"(a1), "r"(a2), "r"(a3),
                  "r"(bf0[jj]), "r"(bf1[jj]),
                  "f"(c0), "f"(c1), "f"(c2), "f"(c3));
            d0 = fmaxf(d0, 0.0f);
            d1 = fmaxf(d1, 0.0f);
            d2 = fmaxf(d2, 0.0f);
            d3 = fmaxf(d3, 0.0f);
            acc0[jj] = fmaf(aF0, d0, acc0[jj]);
            acc0[jj] = fmaf(aF1, d2, acc0[jj]);
            acc1[jj] = fmaf(aF0, d1, acc1[jj]);
            acc1[jj] = fmaf(aF1, d3, acc1[jj]);
        }
    }

    // reduce across the 8 row-groups
#pragma unroll
    for (int jj = 0; jj < 4; jj++) {
        float a = acc0[jj], bq = acc1[jj];
        a  += __shfl_xor_sync(0xffffffffu, a, 4);
        bq += __shfl_xor_sync(0xffffffffu, bq, 4);
        a  += __shfl_xor_sync(0xffffffffu, a, 8);
        bq += __shfl_xor_sync(0xffffffffu, bq, 8);
        a  += __shfl_xor_sync(0xffffffffu, a, 16);
        bq += __shfl_xor_sync(0xffffffffu, bq, 16);
        if (gid == 0)
            *(float2*)&g_part[half][v * H_OUT + (hh * 4 + jj) * 8 + 2 * t4] =
                make_float2(a, bq);
    }

    // ---- fused deterministic combine: last block for this vg sums both halves ----
    __shared__ int s_last;
    __threadfence();
    __syncthreads();
    if (threadIdx.x == 0)
        s_last = (atomicAdd(&g_cnt[vg], 1) == 1);
    __syncthreads();
    if (s_last) {
        __threadfence();   // acquire: make peer block's partials visible
        const int i = vg * 4 * H_OUT + threadIdx.x;   // 256 floats = 4 v * 64 h
        out[i] = g_part[0][i] + g_part[1][i];
        if (threadIdx.x == 0) g_cnt[vg] = 0;          // reset for next replay
    }
}

// ---------- launch ----------
extern "C" void kernel_launch(void* const* d_in, const int* in_sizes, int n_in,
                              void* d_out, int out_size) {
    const int*   adj = (const int*)d_in[0];       // (1,1024,1024) int32
    const float* X   = (const float*)d_in[1];     // (1,1024,32)
    const float* E   = (const float*)d_in[2];     // (1,1024,1024,8)
    const float* W   = (const float*)d_in[3];     // (72,64)
    const float* b   = (const float*)d_in[4];     // (64,)
    float* out = (float*)d_out;                   // (1,1024,64)

    prep_st<<<N_NODES / 4, 256>>>(X, W, b);
    edge_main<<<(N_NODES / 4) * 2, 256>>>(E, adj, W, out);
}

// round 7
// speedup vs baseline: 1.4650x; 1.4650x over previous
#include <cuda_runtime.h>
#include <cuda_bf16.h>
#include <cstdint>

// EdgeConvE: out[v,h] = sum_w A[v,w] * relu(S[v,h] + T[w,h] + sum_e E[v,w,e]*We[e,h])
// N=1024, F=32, E_ATTR=8, H=64.
// R7: strict composition of proven-best parts:
//   prep_st  = R5 version (grid 256, float4 W in smem, Tf scatter)   ~2.5 us
//   edge_main = R3 version VERBATIM (regs ~82, 2 CTA/SM, one wave)   ~16  us
//   combine  = R3 separate kernel                                    ~2.5 us

#define N_NODES 1024
#define F_NODE  32
#define E_ATTR  8
#define H_OUT   64

__device__ __forceinline__ uint32_t to_tf32(float f) {
    uint32_t u; asm("cvt.rna.tf32.f32 %0, %1;" : "=r"(u) : "f"(f)); return u;
}

// ---------- scratch ----------
__device__ float  g_S [N_NODES * H_OUT];             // 256 KB: S[v,h]=X@(Ws-Wd)+b
__device__ float4 g_Tf[(N_NODES / 16) * 8 * 32];     // 256 KB: T in MMA-C frag layout
__device__ float  g_part[2][N_NODES * H_OUT];        // 512 KB: per-half partials

// ---------- kernel 1: S + fragged T (R5 version) ----------
// grid 256, block 256: 4 v per block, one (vl,h) per thread.
__global__ void __launch_bounds__(256)
prep_st(const float* __restrict__ X, const float* __restrict__ W,
        const float* __restrict__ b) {
    __shared__ float ws[2 * F_NODE * H_OUT];   // 16 KB (rows 0..63 of W)
    __shared__ float xs[4][F_NODE];
    const int tid = threadIdx.x;
    const int v0  = blockIdx.x * 4;

    const float4* W4 = reinterpret_cast<const float4*>(W);
    float4* ws4 = reinterpret_cast<float4*>(ws);
#pragma unroll
    for (int i = 0; i < 4; i++) ws4[tid + 256 * i] = W4[tid + 256 * i];
    if (tid < 32)
        reinterpret_cast<float4*>(xs)[tid] =
            reinterpret_cast<const float4*>(X + v0 * F_NODE)[tid];
    __syncthreads();

    const int h  = tid & 63;
    const int vl = tid >> 6;
    float s = __ldg(&b[h]), t = 0.0f;
#pragma unroll
    for (int f = 0; f < F_NODE; f++) {
        float x  = xs[vl][f];
        float wv = ws[f * H_OUT + h];
        float wd = ws[(f + F_NODE) * H_OUT + h];
        s = fmaf(x, wv - wd, s);
        t = fmaf(x, wd, t);
    }
    const int v = v0 + vl;
    g_S[v * H_OUT + h] = s;
    // scatter T into MMA-C frag layout (matches main kernel's read mapping):
    const int wt   = v >> 4;
    const int gid  = v & 7;
    const int rs   = (v >> 3) & 1;
    const int t4   = (h >> 1) & 3;
    const int j    = h >> 3;
    const int elem = (h & 1) + 2 * rs;
    reinterpret_cast<float*>(g_Tf)[(((wt * 8 + j) * 32) + gid * 4 + t4) * 4 + elem] = t;
}

// ---------- kernel 2: main (R3 version, verbatim) ----------
// Block: 8 warps = 8 v's, all scanning the SAME w-half (T reuse via L1).
// Grid: (1024/8) * 2 halves = 256 blocks.
__global__ void __launch_bounds__(256, 2)
edge_main(const float* __restrict__ E, const int* __restrict__ A,
          const float* __restrict__ W) {
    const int vg   = blockIdx.x >> 1;
    const int half = blockIdx.x & 1;
    const int warp = threadIdx.x >> 5;
    const int lane = threadIdx.x & 31;
    const int gid  = lane >> 2;            // 0..7
    const int t4   = lane & 3;             // 0..3
    const int v    = vg * 8 + warp;

    // B frags (We in tf32), loop-invariant
    uint32_t bf0[8], bf1[8];
#pragma unroll
    for (int j = 0; j < 8; j++) {
        bf0[j] = to_tf32(W[(2 * F_NODE + t4)     * H_OUT + j * 8 + gid]);
        bf1[j] = to_tf32(W[(2 * F_NODE + t4 + 4) * H_OUT + j * 8 + gid]);
    }
    // S pairs for this lane's h columns
    float2 sj[8];
#pragma unroll
    for (int j = 0; j < 8; j++)
        sj[j] = *(const float2*)&g_S[v * H_OUT + j * 8 + 2 * t4];

    float acc0[8], acc1[8];
#pragma unroll
    for (int j = 0; j < 8; j++) { acc0[j] = 0.0f; acc1[j] = 0.0f; }

    const float* __restrict__ Ev = E + (size_t)v * (N_NODES * E_ATTR);
    const int*   __restrict__ Av = A + v * N_NODES;
    const float4* __restrict__ Tf = g_Tf;

    const int wt0 = half * 32;
#pragma unroll 2
    for (int wt = wt0; wt < wt0 + 32; wt++) {
        const int r0 = wt * 16 + gid;
        const int r1 = r0 + 8;
        // E frag (tf32)
        uint32_t a0 = to_tf32(Ev[r0 * E_ATTR + t4]);
        uint32_t a1 = to_tf32(Ev[r1 * E_ATTR + t4]);
        uint32_t a2 = to_tf32(Ev[r0 * E_ATTR + t4 + 4]);
        uint32_t a3 = to_tf32(Ev[r1 * E_ATTR + t4 + 4]);
        // adjacency (0/1) for this lane's two w rows
        float aF0 = (float)Av[r0];
        float aF1 = (float)Av[r1];
#pragma unroll
        for (int j = 0; j < 8; j++) {
            float4 c = Tf[(wt * 8 + j) * 32 + lane];   // coalesced 512B/warp
            float c0 = c.x + sj[j].x;
            float c1 = c.y + sj[j].y;
            float c2 = c.z + sj[j].x;
            float c3 = c.w + sj[j].y;
            float d0, d1, d2, d3;
            asm("mma.sync.aligned.m16n8k8.row.col.f32.tf32.tf32.f32 "
                "{%0,%1,%2,%3}, {%4,%5,%6,%7}, {%8,%9}, {%10,%11,%12,%13};"
                : "=f"(d0), "=f"(d1), "=f"(d2), "=f"(d3)
                : "r"(a0), "r"(a1), "r"(a2), "r"(a3),
                  "r"(bf0[j]), "r"(bf1[j]),
                  "f"(c0), "f"(c1), "f"(c2), "f"(c3));
            d0 = fmaxf(d0, 0.0f);
            d1 = fmaxf(d1, 0.0f);
            d2 = fmaxf(d2, 0.0f);
            d3 = fmaxf(d3, 0.0f);
            acc0[j] = fmaf(aF0, d0, acc0[j]);
            acc0[j] = fmaf(aF1, d2, acc0[j]);
            acc1[j] = fmaf(aF0, d1, acc1[j]);
            acc1[j] = fmaf(aF1, d3, acc1[j]);
        }
    }

    // reduce across the 8 row-groups (xor over gid bits: lanes 4,8,16)
#pragma unroll
    for (int j = 0; j < 8; j++) {
        float a = acc0[j], bq = acc1[j];
        a  += __shfl_xor_sync(0xffffffffu, a, 4);
        bq += __shfl_xor_sync(0xffffffffu, bq, 4);
        a  += __shfl_xor_sync(0xffffffffu, a, 8);
        bq += __shfl_xor_sync(0xffffffffu, bq, 8);
        a  += __shfl_xor_sync(0xffffffffu, a, 16);
        bq += __shfl_xor_sync(0xffffffffu, bq, 16);
        if (gid == 0)
            *(float2*)&g_part[half][v * H_OUT + j * 8 + 2 * t4] = make_float2(a, bq);
    }
}

// ---------- kernel 3: deterministic combine (R3 version) ----------
__global__ void combine(float* __restrict__ out) {
    const int i = blockIdx.x * 256 + threadIdx.x;
    out[i] = g_part[0][i] + g_part[1][i];
}

// ---------- launch ----------
extern "C" void kernel_launch(void* const* d_in, const int* in_sizes, int n_in,
                              void* d_out, int out_size) {
    const int*   adj = (const int*)d_in[0];       // (1,1024,1024) int32
    const float* X   = (const float*)d_in[1];     // (1,1024,32)
    const float* E   = (const float*)d_in[2];     // (1,1024,1024,8)
    const float* W   = (const float*)d_in[3];     // (72,64)
    const float* b   = (const float*)d_in[4];     // (64,)
    float* out = (float*)d_out;                   // (1,1024,64)

    prep_st<<<N_NODES / 4, 256>>>(X, W, b);
    edge_main<<<(N_NODES / 8) * 2, 256>>>(E, adj, W);
    combine<<<(N_NODES * H_OUT) / 256, 256>>>(out);
}

// round 8
// speedup vs baseline: 1.4788x; 1.0094x over previous
#include <cuda_runtime.h>
#include <cuda_bf16.h>
#include <cstdint>

// EdgeConvE: out[v,h] = sum_w A[v,w] * relu(S[v,h] + T[w,h] + sum_e E[v,w,e]*We[e,h])
// N=1024, F=32, E_ATTR=8, H=64.
// R8 = R7 + ONE change: K-permuted E fragments (k-slot t4 <-> attr 2t4,
// k-slot t4+4 <-> attr 2t4+1) so E loads are 2x contiguous LDG.64 per wt.
//   prep_st  = R5/R7 version                      ~5 us (latency-bound)
//   edge_main = R3 loop + K-perm E loads          (16.5 -> ~14.5 us predicted)
//   combine  = R3 separate kernel                 ~2.5 us

#define N_NODES 1024
#define F_NODE  32
#define E_ATTR  8
#define H_OUT   64

__device__ __forceinline__ uint32_t to_tf32(float f) {
    uint32_t u; asm("cvt.rna.tf32.f32 %0, %1;" : "=r"(u) : "f"(f)); return u;
}

// ---------- scratch ----------
__device__ float  g_S [N_NODES * H_OUT];             // 256 KB: S[v,h]=X@(Ws-Wd)+b
__device__ float4 g_Tf[(N_NODES / 16) * 8 * 32];     // 256 KB: T in MMA-C frag layout
__device__ float  g_part[2][N_NODES * H_OUT];        // 512 KB: per-half partials

// ---------- kernel 1: S + fragged T ----------
// grid 256, block 256: 4 v per block, one (vl,h) per thread.
__global__ void __launch_bounds__(256)
prep_st(const float* __restrict__ X, const float* __restrict__ W,
        const float* __restrict__ b) {
    __shared__ float ws[2 * F_NODE * H_OUT];   // 16 KB (rows 0..63 of W)
    __shared__ float xs[4][F_NODE];
    const int tid = threadIdx.x;
    const int v0  = blockIdx.x * 4;

    const float4* W4 = reinterpret_cast<const float4*>(W);
    float4* ws4 = reinterpret_cast<float4*>(ws);
#pragma unroll
    for (int i = 0; i < 4; i++) ws4[tid + 256 * i] = W4[tid + 256 * i];
    if (tid < 32)
        reinterpret_cast<float4*>(xs)[tid] =
            reinterpret_cast<const float4*>(X + v0 * F_NODE)[tid];
    __syncthreads();

    const int h  = tid & 63;
    const int vl = tid >> 6;
    float s = __ldg(&b[h]), t = 0.0f;
#pragma unroll
    for (int f = 0; f < F_NODE; f++) {
        float x  = xs[vl][f];
        float wv = ws[f * H_OUT + h];
        float wd = ws[(f + F_NODE) * H_OUT + h];
        s = fmaf(x, wv - wd, s);
        t = fmaf(x, wd, t);
    }
    const int v = v0 + vl;
    g_S[v * H_OUT + h] = s;
    // scatter T into MMA-C frag layout (matches main kernel's read mapping):
    const int wt   = v >> 4;
    const int gid  = v & 7;
    const int rs   = (v >> 3) & 1;
    const int t4   = (h >> 1) & 3;
    const int j    = h >> 3;
    const int elem = (h & 1) + 2 * rs;
    reinterpret_cast<float*>(g_Tf)[(((wt * 8 + j) * 32) + gid * 4 + t4) * 4 + elem] = t;
}

// ---------- kernel 2: main (R3 structure; K-permuted E frags) ----------
// Block: 8 warps = 8 v's, all scanning the SAME w-half (T reuse via L1).
// Grid: (1024/8) * 2 halves = 256 blocks. No launch_bounds cap beyond (256,2).
// K-permutation (consistent in A and B frags; MMA result invariant):
//   k-slot t4   <-> attr 2*t4      k-slot t4+4 <-> attr 2*t4+1
__global__ void __launch_bounds__(256, 2)
edge_main(const float* __restrict__ E, const int* __restrict__ A,
          const float* __restrict__ W) {
    const int vg   = blockIdx.x >> 1;
    const int half = blockIdx.x & 1;
    const int warp = threadIdx.x >> 5;
    const int lane = threadIdx.x & 31;
    const int gid  = lane >> 2;            // 0..7
    const int t4   = lane & 3;             // 0..3
    const int v    = vg * 8 + warp;

    // B frags (We in tf32), permuted-K rows 2t4 and 2t4+1
    uint32_t bf0[8], bf1[8];
#pragma unroll
    for (int j = 0; j < 8; j++) {
        bf0[j] = to_tf32(W[(2 * F_NODE + 2 * t4)     * H_OUT + j * 8 + gid]);
        bf1[j] = to_tf32(W[(2 * F_NODE + 2 * t4 + 1) * H_OUT + j * 8 + gid]);
    }
    // S pairs for this lane's h columns
    float2 sj[8];
#pragma unroll
    for (int j = 0; j < 8; j++)
        sj[j] = *(const float2*)&g_S[v * H_OUT + j * 8 + 2 * t4];

    float acc0[8], acc1[8];
#pragma unroll
    for (int j = 0; j < 8; j++) { acc0[j] = 0.0f; acc1[j] = 0.0f; }

    const float* __restrict__ Ev = E + (size_t)v * (N_NODES * E_ATTR);
    const int*   __restrict__ Av = A + v * N_NODES;
    const float4* __restrict__ Tf = g_Tf;

    const int wt0 = half * 32;
#pragma unroll 2
    for (int wt = wt0; wt < wt0 + 32; wt++) {
        const int r0 = wt * 16 + gid;
        const int r1 = r0 + 8;
        // E A-frag, permuted K: one contiguous LDG.64 per row
        float2 e0 = *(const float2*)&Ev[r0 * E_ATTR + 2 * t4];
        float2 e1 = *(const float2*)&Ev[r1 * E_ATTR + 2 * t4];
        uint32_t a0 = to_tf32(e0.x);   // (row r0, k-slot t4)   = attr 2t4
        uint32_t a2 = to_tf32(e0.y);   // (row r0, k-slot t4+4) = attr 2t4+1
        uint32_t a1 = to_tf32(e1.x);   // (row r1, k-slot t4)
        uint32_t a3 = to_tf32(e1.y);   // (row r1, k-slot t4+4)
        // adjacency (0/1) for this lane's two w rows
        float aF0 = (float)Av[r0];
        float aF1 = (float)Av[r1];
#pragma unroll
        for (int j = 0; j < 8; j++) {
            float4 c = Tf[(wt * 8 + j) * 32 + lane];   // coalesced 512B/warp
            float c0 = c.x + sj[j].x;
            float c1 = c.y + sj[j].y;
            float c2 = c.z + sj[j].x;
            float c3 = c.w + sj[j].y;
            float d0, d1, d2, d3;
            asm("mma.sync.aligned.m16n8k8.row.col.f32.tf32.tf32.f32 "
                "{%0,%1,%2,%3}, {%4,%5,%6,%7}, {%8,%9}, {%10,%11,%12,%13};"
                : "=f"(d0), "=f"(d1), "=f"(d2), "=f"(d3)
                : "r"(a0), "r"(a1), "r"(a2), "r"(a3),
                  "r"(bf0[j]), "r"(bf1[j]),
                  "f"(c0), "f"(c1), "f"(c2), "f"(c3));
            d0 = fmaxf(d0, 0.0f);
            d1 = fmaxf(d1, 0.0f);
            d2 = fmaxf(d2, 0.0f);
            d3 = fmaxf(d3, 0.0f);
            acc0[j] = fmaf(aF0, d0, acc0[j]);
            acc0[j] = fmaf(aF1, d2, acc0[j]);
            acc1[j] = fmaf(aF0, d1, acc1[j]);
            acc1[j] = fmaf(aF1, d3, acc1[j]);
        }
    }

    // reduce across the 8 row-groups (xor over gid bits: lanes 4,8,16)
#pragma unroll
    for (int j = 0; j < 8; j++) {
        float a = acc0[j], bq = acc1[j];
        a  += __shfl_xor_sync(0xffffffffu, a, 4);
        bq += __shfl_xor_sync(0xffffffffu, bq, 4);
        a  += __shfl_xor_sync(0xffffffffu, a, 8);
        bq += __shfl_xor_sync(0xffffffffu, bq, 8);
        a  += __shfl_xor_sync(0xffffffffu, a, 16);
        bq += __shfl_xor_sync(0xffffffffu, bq, 16);
        if (gid == 0)
            *(float2*)&g_part[half][v * H_OUT + j * 8 + 2 * t4] = make_float2(a, bq);
    }
}

// ---------- kernel 3: deterministic combine ----------
__global__ void combine(float* __restrict__ out) {
    const int i = blockIdx.x * 256 + threadIdx.x;
    out[i] = g_part[0][i] + g_part[1][i];
}

// ---------- launch ----------
extern "C" void kernel_launch(void* const* d_in, const int* in_sizes, int n_in,
                              void* d_out, int out_size) {
    const int*   adj = (const int*)d_in[0];       // (1,1024,1024) int32
    const float* X   = (const float*)d_in[1];     // (1,1024,32)
    const float* E   = (const float*)d_in[2];     // (1,1024,1024,8)
    const float* W   = (const float*)d_in[3];     // (72,64)
    const float* b   = (const float*)d_in[4];     // (64,)
    float* out = (float*)d_out;                   // (1,1024,64)

    prep_st<<<N_NODES / 4, 256>>>(X, W, b);
    edge_main<<<(N_NODES / 8) * 2, 256>>>(E, adj, W);
    combine<<<(N_NODES * H_OUT) / 256, 256>>>(out);
}